// round 11
// baseline (speedup 1.0000x reference)
#include <cuda_runtime.h>
#include <math.h>

#define N_NODES 50000
#define N_EDGES 800000
#define DIM 128
#define PAD 128                 // slots per node (Poisson(16): max deg ~45)
#define CSTRIDE 256             // cursor stride = 1024B (full LTS slice spread)

// ---- scratch (__device__ globals: allocation-free) ----
// All state is self-cleaning: cursors + done-counter are reset inside K1's
// embedded hist step each run, so graph replays see pristine state.
__device__ int      g_cursor[N_NODES * CSTRIDE];
__device__ int      g_slots[N_NODES * PAD];     // padded CSR buckets (25.6 MB)
__device__ int      g_deg[N_NODES];             // compact degrees (fresh-written)
__device__ int      g_counts[PAD];              // bincount(deg) (fresh-written)
__device__ unsigned g_done;                     // fill-block completion counter

__device__ __forceinline__ float elu1(float x) {
    return x > 0.f ? x : (__expf(x) - 1.f);
}
__device__ __forceinline__ float4 elu4(float4 a) {
    return make_float4(elu1(a.x), elu1(a.y), elu1(a.z), elu1(a.w));
}
__device__ __forceinline__ void acc4(float4& a, float4 b) {
    a.x += b.x; a.y += b.y; a.z += b.z; a.w += b.w;
}

// ---------------------------------------------------------------------------
// K1: FUSED fill + h-half epilogue + embedded hist.
//  fill blocks [0, FILL_BLOCKS): 8 edges/thread ticket allocation (L2-atomic
//    bound). Last fill block to finish computes deg[] + counts[] from the
//    cursors (overlapping the h-stream blocks), resets cursors + g_done.
//  h blocks [FILL_BLOCKS, +H_BLOCKS): out[:,0:128] = ELU(h), DRAM streaming
//    riding under the atomic phase. deg==0 rows are fixed by gather later.
// ---------------------------------------------------------------------------
#define FILL_BLOCKS ((N_EDGES / 8 + 255) / 256)         // 391
#define H_BLOCKS    (N_NODES * 32 / 256)                // 6250

__global__ void fill_h_kernel(const int4* __restrict__ edge_dst4,
                              const float4* __restrict__ h,
                              float4* __restrict__ out) {
    if (blockIdx.x < FILL_BLOCKS) {
        int i = blockIdx.x * blockDim.x + threadIdx.x;    // over N_EDGES/8
        if (i < N_EDGES / 8) {
            int4 a = edge_dst4[i * 2];
            int4 b = edge_dst4[i * 2 + 1];
            int e = i * 8;
            int s0 = atomicAdd(&g_cursor[(size_t)a.x * CSTRIDE], 1);
            int s1 = atomicAdd(&g_cursor[(size_t)a.y * CSTRIDE], 1);
            int s2 = atomicAdd(&g_cursor[(size_t)a.z * CSTRIDE], 1);
            int s3 = atomicAdd(&g_cursor[(size_t)a.w * CSTRIDE], 1);
            int s4 = atomicAdd(&g_cursor[(size_t)b.x * CSTRIDE], 1);
            int s5 = atomicAdd(&g_cursor[(size_t)b.y * CSTRIDE], 1);
            int s6 = atomicAdd(&g_cursor[(size_t)b.z * CSTRIDE], 1);
            int s7 = atomicAdd(&g_cursor[(size_t)b.w * CSTRIDE], 1);
            if (s0 < PAD) g_slots[a.x * PAD + s0] = e;
            if (s1 < PAD) g_slots[a.y * PAD + s1] = e + 1;
            if (s2 < PAD) g_slots[a.z * PAD + s2] = e + 2;
            if (s3 < PAD) g_slots[a.w * PAD + s3] = e + 3;
            if (s4 < PAD) g_slots[b.x * PAD + s4] = e + 4;
            if (s5 < PAD) g_slots[b.y * PAD + s5] = e + 5;
            if (s6 < PAD) g_slots[b.z * PAD + s6] = e + 6;
            if (s7 < PAD) g_slots[b.w * PAD + s7] = e + 7;
        }

        // ---- embedded hist: last fill block to retire does it ----
        __shared__ int bins[PAD];
        __shared__ int is_last;
        __threadfence();                      // order my atomics before counter
        __syncthreads();
        if (threadIdx.x == 0) {
            unsigned t = atomicAdd(&g_done, 1u);
            is_last = (t == FILL_BLOCKS - 1) ? 1 : 0;
        }
        __syncthreads();
        if (is_last) {
            int t = threadIdx.x;
            if (t < PAD) bins[t] = 0;
            if (t == 0) g_done = 0;           // self-clean for next run
            __syncthreads();
            for (int n = t; n < N_NODES; n += blockDim.x) {
                int d = g_cursor[(size_t)n * CSTRIDE];
                g_cursor[(size_t)n * CSTRIDE] = 0;   // self-clean
                if (d >= PAD) d = PAD - 1;           // unreachable here
                g_deg[n] = d;
                atomicAdd(&bins[d], 1);
            }
            __syncthreads();
            if (t < PAD) g_counts[t] = bins[t];      // single owner: plain store
        }
    } else {
        int idx = (blockIdx.x - FILL_BLOCKS) * blockDim.x + threadIdx.x;
        int node = idx >> 5;                  // one float4 of the h-half/thread
        int lane = idx & 31;
        float4 hv = __ldcs(&h[(size_t)node * 32 + lane]);
        __stcs(&out[(size_t)node * 64 + lane], elu4(hv));
    }
}

// ---------------------------------------------------------------------------
// K2: gather + normalize + ELU -> accum half; zero-fix full row for deg==0.
// One warp per CTA (no block-level degree imbalance).
// ---------------------------------------------------------------------------
__global__ void __launch_bounds__(32)
gather_kernel(const float4* __restrict__ e_lbl,
              float4* __restrict__ out) {
    int node = blockIdx.x;
    int lane = threadIdx.x;

    int d = g_deg[node];
    if (d == 0) {                             // exact DGL semantics: all zeros
        float4 z = make_float4(0.f, 0.f, 0.f, 0.f);
        __stcs(&out[(size_t)node * 64 + lane], z);
        __stcs(&out[(size_t)node * 64 + 32 + lane], z);
        return;
    }

    int cbs = __ldg(&g_counts[d]);
    float4 acc = make_float4(0.f, 0.f, 0.f, 0.f);

    for (int base = 0; base < d; base += 32) {
        int cnt = d - base; if (cnt > 32) cnt = 32;
        int eidx = (lane < cnt) ? __ldg(&g_slots[node * PAD + base + lane]) : 0;

        int j = 0;
        for (; j + 8 <= cnt; j += 8) {
            int f0 = __shfl_sync(0xFFFFFFFFu, eidx, j);
            int f1 = __shfl_sync(0xFFFFFFFFu, eidx, j + 1);
            int f2 = __shfl_sync(0xFFFFFFFFu, eidx, j + 2);
            int f3 = __shfl_sync(0xFFFFFFFFu, eidx, j + 3);
            int f4 = __shfl_sync(0xFFFFFFFFu, eidx, j + 4);
            int f5 = __shfl_sync(0xFFFFFFFFu, eidx, j + 5);
            int f6 = __shfl_sync(0xFFFFFFFFu, eidx, j + 6);
            int f7 = __shfl_sync(0xFFFFFFFFu, eidx, j + 7);
            float4 v0 = __ldcs(&e_lbl[(size_t)f0 * 32 + lane]);
            float4 v1 = __ldcs(&e_lbl[(size_t)f1 * 32 + lane]);
            float4 v2 = __ldcs(&e_lbl[(size_t)f2 * 32 + lane]);
            float4 v3 = __ldcs(&e_lbl[(size_t)f3 * 32 + lane]);
            float4 v4 = __ldcs(&e_lbl[(size_t)f4 * 32 + lane]);
            float4 v5 = __ldcs(&e_lbl[(size_t)f5 * 32 + lane]);
            float4 v6 = __ldcs(&e_lbl[(size_t)f6 * 32 + lane]);
            float4 v7 = __ldcs(&e_lbl[(size_t)f7 * 32 + lane]);
            acc4(acc, v0); acc4(acc, v1); acc4(acc, v2); acc4(acc, v3);
            acc4(acc, v4); acc4(acc, v5); acc4(acc, v6); acc4(acc, v7);
        }
        for (; j < cnt; j++) {
            int f0 = __shfl_sync(0xFFFFFFFFu, eidx, j);
            acc4(acc, __ldcs(&e_lbl[(size_t)f0 * 32 + lane]));
        }
    }
    float inv = __frcp_rn((float)cbs);
    acc.x *= inv; acc.y *= inv; acc.z *= inv; acc.w *= inv;
    __stcs(&out[(size_t)node * 64 + 32 + lane], elu4(acc));
}

// ---------------------------------------------------------------------------
extern "C" void kernel_launch(void* const* d_in, const int* in_sizes, int n_in,
                              void* d_out, int out_size) {
    const float4* h        = (const float4*)d_in[0];
    const float4* e_lbl    = (const float4*)d_in[1];
    const int4*   edge_dst = (const int4*)d_in[2];
    float4*       out      = (float4*)d_out;
    (void)in_sizes; (void)n_in; (void)out_size;

    {   // K1 fused fill + h-half + embedded hist
        fill_h_kernel<<<FILL_BLOCKS + H_BLOCKS, 256>>>(edge_dst, h, out);
    }
    {   // K2 gather + finalize (accum half + deg==0 fix): one warp per CTA
        gather_kernel<<<N_NODES, 32>>>(e_lbl, out);
    }
}

// round 12
// speedup vs baseline: 2.1601x; 2.1601x over previous
#include <cuda_runtime.h>
#include <math.h>

#define N_NODES 50000
#define N_EDGES 800000
#define DIM 128
#define PAD 128                 // slots per node (Poisson(16): max deg ~45)
#define CSTRIDE 256             // cursor stride = 1024B (full LTS slice spread)

// ---- scratch (__device__ globals: allocation-free, self-cleaning) ----
// g_cursor: zeroed at load; reset by gather (after counts flag) each run.
// g_counts / flags: zeroed by K1 block 0 each run (strict kernel ordering).
__device__ int          g_cursor[N_NODES * CSTRIDE];
__device__ int          g_slots[N_NODES * PAD];   // padded CSR buckets (25.6 MB)
__device__ int          g_counts[PAD];            // bincount(deg)
__device__ volatile int g_counts_ready;           // hist -> gather release flag
__device__ unsigned     g_hist_done;              // hist-block completion counter

__device__ __forceinline__ float elu1(float x) {
    return x > 0.f ? x : (__expf(x) - 1.f);
}
__device__ __forceinline__ float4 elu4(float4 a) {
    return make_float4(elu1(a.x), elu1(a.y), elu1(a.z), elu1(a.w));
}
__device__ __forceinline__ void acc4(float4& a, float4 b) {
    a.x += b.x; a.y += b.y; a.z += b.z; a.w += b.w;
}

// ---------------------------------------------------------------------------
// K1: fill (8 edges/thread ticket allocation) + h-half streaming epilogue.
// Block 0 additionally zeroes g_counts and the hist flags for K2.
// ---------------------------------------------------------------------------
#define FILL_BLOCKS ((N_EDGES / 8 + 255) / 256)         // 391
#define H_BLOCKS    (N_NODES * 32 / 256)                // 6250

__global__ void fill_h_kernel(const int4* __restrict__ edge_dst4,
                              const float4* __restrict__ h,
                              float4* __restrict__ out) {
    if (blockIdx.x < FILL_BLOCKS) {
        if (blockIdx.x == 0) {
            if (threadIdx.x < PAD / 4)
                ((int4*)g_counts)[threadIdx.x] = make_int4(0, 0, 0, 0);
            if (threadIdx.x == 0) { g_counts_ready = 0; g_hist_done = 0u; }
        }
        int i = blockIdx.x * blockDim.x + threadIdx.x;    // over N_EDGES/8
        if (i < N_EDGES / 8) {
            int4 a = edge_dst4[i * 2];
            int4 b = edge_dst4[i * 2 + 1];
            int e = i * 8;
            int s0 = atomicAdd(&g_cursor[(size_t)a.x * CSTRIDE], 1);
            int s1 = atomicAdd(&g_cursor[(size_t)a.y * CSTRIDE], 1);
            int s2 = atomicAdd(&g_cursor[(size_t)a.z * CSTRIDE], 1);
            int s3 = atomicAdd(&g_cursor[(size_t)a.w * CSTRIDE], 1);
            int s4 = atomicAdd(&g_cursor[(size_t)b.x * CSTRIDE], 1);
            int s5 = atomicAdd(&g_cursor[(size_t)b.y * CSTRIDE], 1);
            int s6 = atomicAdd(&g_cursor[(size_t)b.z * CSTRIDE], 1);
            int s7 = atomicAdd(&g_cursor[(size_t)b.w * CSTRIDE], 1);
            if (s0 < PAD) g_slots[a.x * PAD + s0] = e;
            if (s1 < PAD) g_slots[a.y * PAD + s1] = e + 1;
            if (s2 < PAD) g_slots[a.z * PAD + s2] = e + 2;
            if (s3 < PAD) g_slots[a.w * PAD + s3] = e + 3;
            if (s4 < PAD) g_slots[b.x * PAD + s4] = e + 4;
            if (s5 < PAD) g_slots[b.y * PAD + s5] = e + 5;
            if (s6 < PAD) g_slots[b.z * PAD + s6] = e + 6;
            if (s7 < PAD) g_slots[b.w * PAD + s7] = e + 7;
        }
    } else {
        int idx = (blockIdx.x - FILL_BLOCKS) * blockDim.x + threadIdx.x;
        int node = idx >> 5;                  // one float4 of the h-half/thread
        int lane = idx & 31;
        float4 hv = __ldcs(&h[(size_t)node * 32 + lane]);
        __stcs(&out[(size_t)node * 64 + lane], elu4(hv));
    }
}

// ---------------------------------------------------------------------------
// K2: merged hist + gather (all 32-thread blocks).
//   Blocks [0, HIST_BLOCKS): parallel bincount over cursors (read-only),
//     release g_counts_ready when the last one finishes. Scheduled in wave 1
//     ahead of every gather block (ID-ordered dispatch) -> no deadlock.
//   Blocks [HIST_BLOCKS, +N_NODES): per-node gather; degree read directly
//     from the cursor; counts consumed only AFTER the flag (post-mainloop,
//     so the wait is ~free); cursor reset after the flag (hist done reading).
// ---------------------------------------------------------------------------
#define HIST_BLOCKS ((N_NODES + 255) / 256)             // 196, 256 nodes each

__global__ void __launch_bounds__(32)
hist_gather_kernel(const float4* __restrict__ e_lbl,
                   float4* __restrict__ out) {
    if (blockIdx.x < HIST_BLOCKS) {
        // ---- hist role: 32 threads, 256 nodes per block, smem bins ----
        __shared__ int bins[PAD];
        int t = threadIdx.x;
        #pragma unroll
        for (int k = 0; k < PAD / 32; k++) bins[t + k * 32] = 0;
        __syncwarp();

        int nbase = blockIdx.x * 256;
        #pragma unroll
        for (int k = 0; k < 8; k++) {
            int n = nbase + k * 32 + t;
            if (n < N_NODES) {
                int d = g_cursor[(size_t)n * CSTRIDE];   // read-only here
                if (d >= PAD) d = PAD - 1;               // unreachable
                atomicAdd(&bins[d], 1);
            }
        }
        __syncwarp();
        #pragma unroll
        for (int k = 0; k < PAD / 32; k++) {
            int c = bins[t + k * 32];
            if (c) atomicAdd(&g_counts[t + k * 32], c);
        }
        __threadfence();
        __syncwarp();
        if (t == 0) {
            unsigned done = atomicAdd(&g_hist_done, 1u);
            if (done == HIST_BLOCKS - 1) {
                __threadfence();
                g_counts_ready = 1;                      // release
            }
        }
        return;
    }

    // ---- gather role ----
    int node = blockIdx.x - HIST_BLOCKS;
    int lane = threadIdx.x;

    int d = __shfl_sync(0xFFFFFFFFu, (lane == 0) ? g_cursor[(size_t)node * CSTRIDE] : 0, 0);

    if (d == 0) {                             // exact DGL semantics: all zeros
        float4 z = make_float4(0.f, 0.f, 0.f, 0.f);
        __stcs(&out[(size_t)node * 64 + lane], z);
        __stcs(&out[(size_t)node * 64 + 32 + lane], z);
        return;
    }
    if (d >= PAD) d = PAD - 1;                // unreachable

    float4 acc = make_float4(0.f, 0.f, 0.f, 0.f);
    for (int base = 0; base < d; base += 32) {
        int cnt = d - base; if (cnt > 32) cnt = 32;
        int eidx = (lane < cnt) ? __ldg(&g_slots[node * PAD + base + lane]) : 0;

        int j = 0;
        for (; j + 8 <= cnt; j += 8) {
            int f0 = __shfl_sync(0xFFFFFFFFu, eidx, j);
            int f1 = __shfl_sync(0xFFFFFFFFu, eidx, j + 1);
            int f2 = __shfl_sync(0xFFFFFFFFu, eidx, j + 2);
            int f3 = __shfl_sync(0xFFFFFFFFu, eidx, j + 3);
            int f4 = __shfl_sync(0xFFFFFFFFu, eidx, j + 4);
            int f5 = __shfl_sync(0xFFFFFFFFu, eidx, j + 5);
            int f6 = __shfl_sync(0xFFFFFFFFu, eidx, j + 6);
            int f7 = __shfl_sync(0xFFFFFFFFu, eidx, j + 7);
            float4 v0 = __ldcs(&e_lbl[(size_t)f0 * 32 + lane]);
            float4 v1 = __ldcs(&e_lbl[(size_t)f1 * 32 + lane]);
            float4 v2 = __ldcs(&e_lbl[(size_t)f2 * 32 + lane]);
            float4 v3 = __ldcs(&e_lbl[(size_t)f3 * 32 + lane]);
            float4 v4 = __ldcs(&e_lbl[(size_t)f4 * 32 + lane]);
            float4 v5 = __ldcs(&e_lbl[(size_t)f5 * 32 + lane]);
            float4 v6 = __ldcs(&e_lbl[(size_t)f6 * 32 + lane]);
            float4 v7 = __ldcs(&e_lbl[(size_t)f7 * 32 + lane]);
            acc4(acc, v0); acc4(acc, v1); acc4(acc, v2); acc4(acc, v3);
            acc4(acc, v4); acc4(acc, v5); acc4(acc, v6); acc4(acc, v7);
        }
        for (; j < cnt; j++) {
            int f0 = __shfl_sync(0xFFFFFFFFu, eidx, j);
            acc4(acc, __ldcs(&e_lbl[(size_t)f0 * 32 + lane]));
        }
    }

    // wait for counts (hist finished ages ago for all but the earliest warps)
    if (lane == 0) {
        while (g_counts_ready == 0) { __nanosleep(64); }
        g_cursor[(size_t)node * CSTRIDE] = 0;    // self-clean (hist done reading)
    }
    __syncwarp();
    __threadfence();                             // acquire side

    int cbs = __ldg(&g_counts[d]);
    float inv = __frcp_rn((float)cbs);
    acc.x *= inv; acc.y *= inv; acc.z *= inv; acc.w *= inv;
    __stcs(&out[(size_t)node * 64 + 32 + lane], elu4(acc));
}

// ---------------------------------------------------------------------------
extern "C" void kernel_launch(void* const* d_in, const int* in_sizes, int n_in,
                              void* d_out, int out_size) {
    const float4* h        = (const float4*)d_in[0];
    const float4* e_lbl    = (const float4*)d_in[1];
    const int4*   edge_dst = (const int4*)d_in[2];
    float4*       out      = (float4*)d_out;
    (void)in_sizes; (void)n_in; (void)out_size;

    {   // K1 fill + h-half (+ counts/flag zeroing)
        fill_h_kernel<<<FILL_BLOCKS + H_BLOCKS, 256>>>(edge_dst, h, out);
    }
    {   // K2 merged hist + gather
        hist_gather_kernel<<<HIST_BLOCKS + N_NODES, 32>>>(e_lbl, out);
    }
}

// round 13
// speedup vs baseline: 2.2493x; 1.0413x over previous
#include <cuda_runtime.h>
#include <math.h>

#define N_NODES 50000
#define N_EDGES 800000
#define DIM 128
#define PAD 128                 // slots per node (Poisson(16): max deg ~45)
#define CSTRIDE 256             // cursor stride = 1024B (full LTS slice spread)

// ---- scratch (__device__ globals: allocation-free, self-cleaning) ----
// g_cursor: zero at load; reset by the hist role inside K1 each run.
// g_fill_done / g_hist_done: reset by the last hist block each run.
__device__ int      g_cursor[N_NODES * CSTRIDE];
__device__ int      g_slots[N_NODES * PAD];     // padded CSR buckets (25.6 MB)
__device__ int      g_deg[N_NODES];             // compact degrees (fresh-written)
__device__ int      g_counts[PAD];              // bincount(deg)
__device__ unsigned g_fill_done;
__device__ unsigned g_hist_done;

__device__ __forceinline__ float elu1(float x) {
    return x > 0.f ? x : (__expf(x) - 1.f);
}
__device__ __forceinline__ float4 elu4(float4 a) {
    return make_float4(elu1(a.x), elu1(a.y), elu1(a.z), elu1(a.w));
}
__device__ __forceinline__ void acc4(float4& a, float4 b) {
    a.x += b.x; a.y += b.y; a.z += b.z; a.w += b.w;
}

// ---------------------------------------------------------------------------
// K1: three block roles (ID-ordered; all roles resident in wave 1):
//   [0, FILL)          fill: 8 edges/thread ticket allocation (L2-atomic bound)
//   [FILL, FILL+HIST)  hist: spin on fill-done counter, then PARALLEL bincount
//                      (196 blocks x 256 nodes) + compact deg + cursor reset
//   [FILL+HIST, ...)   h-stream: out[:,0:128] = ELU(h) rides the idle DRAM pipe
// ---------------------------------------------------------------------------
#define FILL_BLOCKS ((N_EDGES / 8 + 255) / 256)         // 391
#define HIST_BLOCKS ((N_NODES + 255) / 256)             // 196
#define H_BLOCKS    (N_NODES * 32 / 256)                // 6250

__global__ void fused_k1(const int4* __restrict__ edge_dst4,
                         const float4* __restrict__ h,
                         float4* __restrict__ out) {
    if (blockIdx.x < FILL_BLOCKS) {
        // ---------------- fill role ----------------
        if (blockIdx.x == 0 && threadIdx.x < PAD / 4) {
            ((int4*)g_counts)[threadIdx.x] = make_int4(0, 0, 0, 0);
        }
        int i = blockIdx.x * blockDim.x + threadIdx.x;    // over N_EDGES/8
        if (i < N_EDGES / 8) {
            int4 a = edge_dst4[i * 2];
            int4 b = edge_dst4[i * 2 + 1];
            int e = i * 8;
            int s0 = atomicAdd(&g_cursor[(size_t)a.x * CSTRIDE], 1);
            int s1 = atomicAdd(&g_cursor[(size_t)a.y * CSTRIDE], 1);
            int s2 = atomicAdd(&g_cursor[(size_t)a.z * CSTRIDE], 1);
            int s3 = atomicAdd(&g_cursor[(size_t)a.w * CSTRIDE], 1);
            int s4 = atomicAdd(&g_cursor[(size_t)b.x * CSTRIDE], 1);
            int s5 = atomicAdd(&g_cursor[(size_t)b.y * CSTRIDE], 1);
            int s6 = atomicAdd(&g_cursor[(size_t)b.z * CSTRIDE], 1);
            int s7 = atomicAdd(&g_cursor[(size_t)b.w * CSTRIDE], 1);
            if (s0 < PAD) g_slots[a.x * PAD + s0] = e;
            if (s1 < PAD) g_slots[a.y * PAD + s1] = e + 1;
            if (s2 < PAD) g_slots[a.z * PAD + s2] = e + 2;
            if (s3 < PAD) g_slots[a.w * PAD + s3] = e + 3;
            if (s4 < PAD) g_slots[b.x * PAD + s4] = e + 4;
            if (s5 < PAD) g_slots[b.y * PAD + s5] = e + 5;
            if (s6 < PAD) g_slots[b.z * PAD + s6] = e + 6;
            if (s7 < PAD) g_slots[b.w * PAD + s7] = e + 7;
        }
        // canonical publish: per-thread fence, barrier, single bump
        __threadfence();
        __syncthreads();
        if (threadIdx.x == 0) atomicAdd(&g_fill_done, 1u);

    } else if (blockIdx.x < FILL_BLOCKS + HIST_BLOCKS) {
        // ---------------- hist role (parallel, spins on fill) ----------------
        __shared__ int bins[PAD];
        int t = threadIdx.x;
        if (t < PAD) bins[t] = 0;
        if (t == 0) {
            volatile unsigned* fd = &g_fill_done;
            while (*fd < (unsigned)FILL_BLOCKS) { __nanosleep(128); }
        }
        __syncthreads();
        __threadfence();                       // acquire side

        int n = (blockIdx.x - FILL_BLOCKS) * 256 + t;
        if (n < N_NODES) {
            int d = g_cursor[(size_t)n * CSTRIDE];
            g_cursor[(size_t)n * CSTRIDE] = 0;   // self-clean for next run
            if (d >= PAD) d = PAD - 1;           // unreachable for this data
            g_deg[n] = d;
            atomicAdd(&bins[d], 1);
        }
        __syncthreads();
        if (t < PAD) {
            int c = bins[t];
            if (c) atomicAdd(&g_counts[t], c);
        }
        __threadfence();
        __syncthreads();
        if (t == 0) {
            unsigned done = atomicAdd(&g_hist_done, 1u);
            if (done == HIST_BLOCKS - 1) {       // last hist block: reset flags
                g_fill_done = 0u;
                g_hist_done = 0u;
            }
        }

    } else {
        // ---------------- h-stream role ----------------
        int idx = (blockIdx.x - FILL_BLOCKS - HIST_BLOCKS) * blockDim.x + threadIdx.x;
        int node = idx >> 5;                  // one float4 of the h-half/thread
        int lane = idx & 31;
        float4 hv = __ldcs(&h[(size_t)node * 32 + lane]);
        __stcs(&out[(size_t)node * 64 + lane], elu4(hv));
    }
}

// ---------------------------------------------------------------------------
// K2: gather + normalize + ELU -> accum half; zero-fix full row for deg==0.
// One warp per CTA; compact g_deg reads; no bookkeeping in the hot loop.
// ---------------------------------------------------------------------------
__global__ void __launch_bounds__(32)
gather_kernel(const float4* __restrict__ e_lbl,
              float4* __restrict__ out) {
    int node = blockIdx.x;
    int lane = threadIdx.x;

    int d = g_deg[node];
    if (d == 0) {                             // exact DGL semantics: all zeros
        float4 z = make_float4(0.f, 0.f, 0.f, 0.f);
        __stcs(&out[(size_t)node * 64 + lane], z);
        __stcs(&out[(size_t)node * 64 + 32 + lane], z);
        return;
    }

    int cbs = __ldg(&g_counts[d]);
    float4 acc = make_float4(0.f, 0.f, 0.f, 0.f);

    for (int base = 0; base < d; base += 32) {
        int cnt = d - base; if (cnt > 32) cnt = 32;
        int eidx = (lane < cnt) ? __ldg(&g_slots[node * PAD + base + lane]) : 0;

        int j = 0;
        for (; j + 8 <= cnt; j += 8) {
            int f0 = __shfl_sync(0xFFFFFFFFu, eidx, j);
            int f1 = __shfl_sync(0xFFFFFFFFu, eidx, j + 1);
            int f2 = __shfl_sync(0xFFFFFFFFu, eidx, j + 2);
            int f3 = __shfl_sync(0xFFFFFFFFu, eidx, j + 3);
            int f4 = __shfl_sync(0xFFFFFFFFu, eidx, j + 4);
            int f5 = __shfl_sync(0xFFFFFFFFu, eidx, j + 5);
            int f6 = __shfl_sync(0xFFFFFFFFu, eidx, j + 6);
            int f7 = __shfl_sync(0xFFFFFFFFu, eidx, j + 7);
            float4 v0 = __ldcs(&e_lbl[(size_t)f0 * 32 + lane]);
            float4 v1 = __ldcs(&e_lbl[(size_t)f1 * 32 + lane]);
            float4 v2 = __ldcs(&e_lbl[(size_t)f2 * 32 + lane]);
            float4 v3 = __ldcs(&e_lbl[(size_t)f3 * 32 + lane]);
            float4 v4 = __ldcs(&e_lbl[(size_t)f4 * 32 + lane]);
            float4 v5 = __ldcs(&e_lbl[(size_t)f5 * 32 + lane]);
            float4 v6 = __ldcs(&e_lbl[(size_t)f6 * 32 + lane]);
            float4 v7 = __ldcs(&e_lbl[(size_t)f7 * 32 + lane]);
            acc4(acc, v0); acc4(acc, v1); acc4(acc, v2); acc4(acc, v3);
            acc4(acc, v4); acc4(acc, v5); acc4(acc, v6); acc4(acc, v7);
        }
        for (; j < cnt; j++) {
            int f0 = __shfl_sync(0xFFFFFFFFu, eidx, j);
            acc4(acc, __ldcs(&e_lbl[(size_t)f0 * 32 + lane]));
        }
    }
    float inv = __frcp_rn((float)cbs);
    acc.x *= inv; acc.y *= inv; acc.z *= inv; acc.w *= inv;
    __stcs(&out[(size_t)node * 64 + 32 + lane], elu4(acc));
}

// ---------------------------------------------------------------------------
extern "C" void kernel_launch(void* const* d_in, const int* in_sizes, int n_in,
                              void* d_out, int out_size) {
    const float4* h        = (const float4*)d_in[0];
    const float4* e_lbl    = (const float4*)d_in[1];
    const int4*   edge_dst = (const int4*)d_in[2];
    float4*       out      = (float4*)d_out;
    (void)in_sizes; (void)n_in; (void)out_size;

    {   // K1: fill + parallel embedded hist + h-half streaming
        fused_k1<<<FILL_BLOCKS + HIST_BLOCKS + H_BLOCKS, 256>>>(edge_dst, h, out);
    }
    {   // K2: gather + finalize (accum half + deg==0 fix): one warp per CTA
        gather_kernel<<<N_NODES, 32>>>(e_lbl, out);
    }
}